// round 3
// baseline (speedup 1.0000x reference)
#include <cuda_runtime.h>

// Problem constants (fixed by the dataset)
#define NMAX    50000
#define EMAX    800000
#define ETOTMAX (EMAX + NMAX)
#define FEAT    128
#define HEADS   4
#define CH      32
#define NG      64
#define NCLS    10
#define NEG     0.2f
#define NLAYERS 3

// -------- static scratch (no allocations allowed); 16B-aligned for vector access --------
__device__ __align__(16) float g_h   [NMAX * FEAT];     // activations between layers
__device__ __align__(16) float g_xl  [NMAX * FEAT];     // W_l x + b_l
__device__ __align__(16) float g_xr  [NMAX * FEAT];     // W_r x + b_r
__device__ __align__(16) float g_acc [NMAX * FEAT];     // aggregation accumulator (init = bias)
__device__ __align__(16) float g_sc  [ETOTMAX * HEADS]; // edge scores / exp scores
__device__ __align__(16) float g_max [NMAX * HEADS];    // segment max per (dst, head)
__device__ __align__(16) float g_den [NMAX * HEADS];    // segment sum of exp, then reciprocal
__device__ __align__(16) float g_pool[NG * FEAT];       // graph pooling sums
__device__ __align__(16) float g_cnt [NG];              // nodes per graph

// -------- helpers --------
__device__ __forceinline__ void atomic_max_f(float* addr, float v) {
    int iv = __float_as_int(v);
    if (iv == (int)0x80000000) iv = 0;  // normalize -0.0 -> +0.0
    if (iv >= 0) atomicMax((int*)addr, iv);
    else         atomicMin((unsigned int*)addr, (unsigned int)iv);
}

// vector reduction-add to global (sm_90+): 4x fewer L2 atomic ops than scalar
__device__ __forceinline__ void red_add4(float* addr, float a, float b, float c, float d) {
    asm volatile("red.global.add.v4.f32 [%0], {%1, %2, %3, %4};"
                 :: "l"(addr), "f"(a), "f"(b), "f"(c), "f"(d) : "memory");
}

__device__ __forceinline__ float elu_f(float v) {
    return v > 0.0f ? v : expm1f(v);
}

// -------- per-layer kernels --------

// init accumulator to bias, max to -inf, den to 0
__global__ void init_layer_k(const float* __restrict__ bias, int n) {
    int i = blockIdx.x * blockDim.x + threadIdx.x;
    if (i < n * FEAT) g_acc[i] = bias[i & (FEAT - 1)];
    if (i < n * HEADS) {
        g_max[i] = __int_as_float(0xff800000); // -inf
        g_den[i] = 0.0f;
    }
}

// xl = act @ Wl + bl ; xr = act @ Wr + br    (both in one pass)
// block: 128 threads (one per output column), 16 nodes per block
__global__ void gemm_lr_k(const float* __restrict__ x_in, int use_x,
                          const float* __restrict__ Wl, const float* __restrict__ Wr,
                          const float* __restrict__ bl, const float* __restrict__ br,
                          int n) {
    __shared__ float xs[16][FEAT];
    const float* act = use_x ? x_in : g_h;
    int col  = threadIdx.x;
    int base = blockIdx.x * 16;
    #pragma unroll
    for (int r = 0; r < 16; r++) {
        int node = base + r;
        xs[r][col] = (node < n) ? act[node * FEAT + col] : 0.0f;
    }
    __syncthreads();

    float al[16], ar[16];
    #pragma unroll
    for (int r = 0; r < 16; r++) { al[r] = 0.0f; ar[r] = 0.0f; }

    #pragma unroll 4
    for (int k = 0; k < FEAT; k++) {
        float wl = Wl[k * FEAT + col];
        float wr = Wr[k * FEAT + col];
        #pragma unroll
        for (int r = 0; r < 16; r++) {
            float xv = xs[r][k];
            al[r] = fmaf(xv, wl, al[r]);
            ar[r] = fmaf(xv, wr, ar[r]);
        }
    }
    float bL = bl[col], bR = br[col];
    #pragma unroll
    for (int r = 0; r < 16; r++) {
        int node = base + r;
        if (node < n) {
            g_xl[node * FEAT + col] = al[r] + bL;
            g_xr[node * FEAT + col] = ar[r] + bR;
        }
    }
}

// per-edge attention scores e[h] = sum_c att[h][c] * leaky_relu(xl[src]+xr[dst])
// one warp per edge; atomicMax into per-(dst,head) running max
__global__ void edge_score_k(const int* __restrict__ src_a,
                             const int* __restrict__ dst_a,
                             int E, int Etot,
                             const float* __restrict__ att) {
    int wid  = (blockIdx.x * blockDim.x + threadIdx.x) >> 5;
    int lane = threadIdx.x & 31;
    if (wid >= Etot) return;
    int s, d;
    if (wid < E) { s = src_a[wid]; d = dst_a[wid]; }
    else         { s = wid - E; d = s; }

    float v[HEADS];
    #pragma unroll
    for (int h = 0; h < HEADS; h++) {
        int idx = h * CH + lane;
        float z = g_xl[s * FEAT + idx] + g_xr[d * FEAT + idx];
        z = z > 0.0f ? z : NEG * z;
        v[h] = z * att[h * CH + lane];
    }
    #pragma unroll
    for (int off = 16; off; off >>= 1) {
        #pragma unroll
        for (int h = 0; h < HEADS; h++)
            v[h] += __shfl_xor_sync(0xffffffffu, v[h], off);
    }
    if (lane < HEADS) {
        float e = v[lane];
        g_sc[wid * HEADS + lane] = e;
        atomic_max_f(&g_max[d * HEADS + lane], e);
    }
}

// ee = exp(e - max[dst][h]); accumulate denominator
__global__ void edge_exp_k(const int* __restrict__ dst_a, int E, int Etot) {
    int i = blockIdx.x * blockDim.x + threadIdx.x;
    if (i >= Etot * HEADS) return;
    int e = i >> 2, h = i & 3;
    int d = (e < E) ? dst_a[e] : e - E;
    float ee = expf(g_sc[i] - g_max[d * HEADS + h]);
    g_sc[i] = ee;
    atomicAdd(&g_den[d * HEADS + h], ee);
}

__global__ void inv_den_k(int n) {
    int i = blockIdx.x * blockDim.x + threadIdx.x;
    if (i < n * HEADS) g_den[i] = 1.0f / g_den[i];
}

// out[dst] += xl[src] * alpha   (warp per edge; lane -> head=lane/8, 4 channels)
__global__ void edge_agg_k(const int* __restrict__ src_a,
                           const int* __restrict__ dst_a,
                           int E, int Etot) {
    int wid  = (blockIdx.x * blockDim.x + threadIdx.x) >> 5;
    int lane = threadIdx.x & 31;
    if (wid >= Etot) return;
    int s, d;
    if (wid < E) { s = src_a[wid]; d = dst_a[wid]; }
    else         { s = wid - E; d = s; }

    int h = lane >> 3;
    int j = (lane & 7) * 4;
    float alpha = g_sc[wid * HEADS + h] * g_den[d * HEADS + h];
    const float4 xv = *(const float4*)&g_xl[s * FEAT + h * CH + j];
    red_add4(&g_acc[d * FEAT + h * CH + j],
             xv.x * alpha, xv.y * alpha, xv.z * alpha, xv.w * alpha);
}

// h = elu(acc)  (acc already contains bias + aggregation)
__global__ void elu_k(int n) {
    int i = blockIdx.x * blockDim.x + threadIdx.x;
    if (i < n * FEAT) g_h[i] = elu_f(g_acc[i]);
}

// -------- pooling + classifier --------
__global__ void pool_zero_k() {
    int i = blockIdx.x * blockDim.x + threadIdx.x;
    if (i < NG * FEAT) g_pool[i] = 0.0f;
    if (i < NG)        g_cnt[i]  = 0.0f;
}

// warp per node: sum features into its graph slot, count nodes
__global__ void pool_sum_k(const int* __restrict__ batch, int n) {
    int wid  = (blockIdx.x * blockDim.x + threadIdx.x) >> 5;
    int lane = threadIdx.x & 31;
    if (wid >= n) return;
    int b = batch[wid];
    const float4 v = *(const float4*)&g_h[wid * FEAT + lane * 4];
    red_add4(&g_pool[b * FEAT + lane * 4], v.x, v.y, v.z, v.w);
    if (lane == 0) atomicAdd(&g_cnt[b], 1.0f);
}

// block per graph: logits = elu(pooled @ W + b); log_softmax over 10 classes
__global__ void head_k(const float* __restrict__ lin_w,
                       const float* __restrict__ lin_b,
                       float* __restrict__ out) {
    int g = blockIdx.x;
    int k = threadIdx.x;
    __shared__ float lg[NCLS];
    float inv = 1.0f / fmaxf(g_cnt[g], 1.0f);
    if (k < NCLS) {
        float acc = lin_b[k];
        for (int c = 0; c < FEAT; c++)
            acc = fmaf(g_pool[g * FEAT + c] * inv, lin_w[c * NCLS + k], acc);
        lg[k] = elu_f(acc);
    }
    __syncthreads();
    if (k < NCLS) {
        float m = lg[0];
        #pragma unroll
        for (int j = 1; j < NCLS; j++) m = fmaxf(m, lg[j]);
        float ssum = 0.0f;
        #pragma unroll
        for (int j = 0; j < NCLS; j++) ssum += expf(lg[j] - m);
        out[g * NCLS + k] = lg[k] - m - logf(ssum);
    }
}

// -------- launch --------
extern "C" void kernel_launch(void* const* d_in, const int* in_sizes, int n_in,
                              void* d_out, int out_size) {
    const float* x     = (const float*)d_in[0];
    const int*   ei    = (const int*)d_in[1];     // int32 (JAX x64 disabled)
    const int*   batch = (const int*)d_in[2];     // int32
    const float* Wl    = (const float*)d_in[3];
    const float* Wr    = (const float*)d_in[4];
    const float* bl    = (const float*)d_in[5];
    const float* br    = (const float*)d_in[6];
    const float* att   = (const float*)d_in[7];
    const float* bias  = (const float*)d_in[8];
    const float* lin_w = (const float*)d_in[9];
    const float* lin_b = (const float*)d_in[10];
    float*       out   = (float*)d_out;

    int E    = in_sizes[1] / 2;
    int n    = in_sizes[0] / FEAT;
    int Etot = E + n;

    const int* src = ei;
    const int* dst = ei + E;

    const int T = 256;
    int g_elem  = (n * FEAT + T - 1) / T;              // elementwise over N*128
    int g_edgeW = (int)(((long long)Etot * 32 + T - 1) / T);  // warp per edge
    int g_edgeH = (Etot * HEADS + T - 1) / T;          // thread per (edge,head)
    int g_nh    = (n * HEADS + T - 1) / T;
    int g_gemm  = (n + 15) / 16;
    int g_poolW = (int)(((long long)n * 32 + T - 1) / T);

    for (int l = 0; l < NLAYERS; l++) {
        init_layer_k<<<g_elem, T>>>(bias + l * FEAT, n);
        gemm_lr_k<<<g_gemm, 128>>>(x, (l == 0) ? 1 : 0,
                                   Wl + l * FEAT * FEAT, Wr + l * FEAT * FEAT,
                                   bl + l * FEAT, br + l * FEAT, n);
        edge_score_k<<<g_edgeW, T>>>(src, dst, E, Etot, att + l * HEADS * CH);
        edge_exp_k<<<g_edgeH, T>>>(dst, E, Etot);
        inv_den_k<<<g_nh, T>>>(n);
        edge_agg_k<<<g_edgeW, T>>>(src, dst, E, Etot);
        elu_k<<<g_elem, T>>>(n);
    }

    pool_zero_k<<<(NG * FEAT + T - 1) / T, T>>>();
    pool_sum_k<<<g_poolW, T>>>(batch, n);
    head_k<<<NG, 32>>>(lin_w, lin_b, out);
}